// round 7
// baseline (speedup 1.0000x reference)
#include <cuda_runtime.h>

// RoiAlign FPN: B=2, N=1000, CROP=7x7, C=256, levels 256/128/64/32/16 (NHWC f32).
// 296 blocks x 448 threads; each block owns a contiguous batch of 6-7 boxes.
// Phase 1: one thread per (box,pixel) computes all <=343 param sets into smem.
// Phase 2: 7 pixels/iter x 64 float4 channel groups, nb*7 iterations, loads
// software-pipelined across box boundaries (8 LDG.128 in flight per thread).

#define C4 64  // 256 channels / 4

__global__ __launch_bounds__(448, 2) void roialign_kernel(
    const float* __restrict__ boxes,
    const float* __restrict__ f0, const float* __restrict__ f1,
    const float* __restrict__ f2, const float* __restrict__ f3,
    const float* __restrict__ f4,
    const int*   __restrict__ image_shape,
    float*       __restrict__ out,
    int N, int BN, int chunk, int rem)
{
    __shared__ float4 s_a[343];                // corner indices (int bitcast)
    __shared__ float4 s_b[343];                // lx, ly, okf, 0
    __shared__ const float4* s_fp[7];          // per-box level base pointer

    const int bid = blockIdx.x;
    const int tid = threadIdx.x;

    // contiguous box range for this block: first `rem` blocks get chunk+1
    const int start = bid * chunk + min(bid, rem);
    const int nb    = chunk + (bid < rem ? 1 : 0);   // <= 7

    // ---------------- Phase 1: params for all nb*49 pixels -------------------
    if (tid < nb * 49) {
        const int bl   = tid / 49;             // box slot 0..nb-1
        const int pixl = tid % 49;
        const int boxg = start + bl;

        // NOTE: reference unpacks boxes[:,0] as "y1" though setup stacked
        // [x1,y1,x2,y2]; features are square so it's a consistent transpose.
        const float a0 = __ldg(boxes + (size_t)boxg * 4 + 0);
        const float a1 = __ldg(boxes + (size_t)boxg * 4 + 1);
        const float a2 = __ldg(boxes + (size_t)boxg * 4 + 2);
        const float a3 = __ldg(boxes + (size_t)boxg * 4 + 3);

        // lvl = clip(round(log2(sqrt(h*w) / (56/sqrt(area)))), 0, 4)
        const float h     = a3 - a1;
        const float w     = a2 - a0;
        const float area  = (float)(image_shape[0] * image_shape[1]);
        const float denom = 56.0f / sqrtf(area);
        int lvl = (int)rintf(log2f(sqrtf(h * w) / denom));  // round-half-even
        lvl = min(max(lvl, 0), 4);

        const int S = 256 >> lvl;
        const float* feat = (lvl == 0) ? f0 : (lvl == 1) ? f1
                          : (lvl == 2) ? f2 : (lvl == 3) ? f3 : f4;
        if (pixl == 0) s_fp[bl] = (const float4*)feat;

        const float Hf = (float)(S - 1);
        const int gy = pixl / 7;
        const int gx = pixl % 7;

        // Exact reference op order: ys = y1*Hf + gy*((y2-y1)*Hf/6)
        const float ys = a0 * Hf + (float)gy * (((a2 - a0) * Hf) / 6.0f);
        const float xs = a1 * Hf + (float)gx * (((a3 - a1) * Hf) / 6.0f);

        const float y0f = floorf(ys);
        const float x0f = floorf(xs);
        const float ly  = ys - y0f;
        const float lx  = xs - x0f;

        const int y0 = (int)fminf(fmaxf(y0f,        0.0f), Hf);
        const int y1 = (int)fminf(fmaxf(y0f + 1.0f, 0.0f), Hf);
        const int x0 = (int)fminf(fmaxf(x0f,        0.0f), Hf);
        const int x1 = (int)fminf(fmaxf(x0f + 1.0f, 0.0f), Hf);

        const float okf = ((ys >= 0.0f) & (ys <= Hf) &
                           (xs >= 0.0f) & (xs <= Hf)) ? 1.0f : 0.0f;

        const int bS = (boxg / N) * S;
        const int r0 = (bS + y0) * S;
        const int r1 = (bS + y1) * S;
        // flat indices in float4 units (max ~8.4M, int32-safe)
        s_a[tid] = make_float4(__int_as_float((r0 + x0) * C4),
                               __int_as_float((r0 + x1) * C4),
                               __int_as_float((r1 + x0) * C4),
                               __int_as_float((r1 + x1) * C4));
        s_b[tid] = make_float4(lx, ly, okf, 0.0f);
    }
    __syncthreads();

    // ---------------- Phase 2: pipelined gather + lerp -----------------------
    // q = it*7 + psub indexes (box, pixel) linearly; box = it/7 (uniform per
    // iteration since 49 = 7*7 aligns box boundaries to iteration groups).
    const int psub  = tid >> 6;       // pixel sub-slot 0..6
    const int c     = tid & 63;       // float4 channel group 0..63
    const int iters = nb * 7;
    float4* __restrict__ out4 = (float4*)out + (long)start * 49 * C4 + c;

    // Prologue: pixel group 0 (box 0)
    int p = psub;
    const float4* __restrict__ fp = s_fp[0];
    float4 qa = s_a[p];
    float4 qb = s_b[p];
    float4 v00 = __ldg(fp + __float_as_int(qa.x) + c);
    float4 v01 = __ldg(fp + __float_as_int(qa.y) + c);
    float4 v10 = __ldg(fp + __float_as_int(qa.z) + c);
    float4 v11 = __ldg(fp + __float_as_int(qa.w) + c);

    #pragma unroll 1
    for (int it = 0; it < iters; ++it) {
        const float4* nfp = fp;
        float4 nqa, nqb, n00, n01, n10, n11;
        if (it + 1 < iters) {         // prefetch next pixel group's corners
            nfp = s_fp[(it + 1) / 7];
            nqa = s_a[p + 7];
            nqb = s_b[p + 7];
            n00 = __ldg(nfp + __float_as_int(nqa.x) + c);
            n01 = __ldg(nfp + __float_as_int(nqa.y) + c);
            n10 = __ldg(nfp + __float_as_int(nqa.z) + c);
            n11 = __ldg(nfp + __float_as_int(nqa.w) + c);
        }

        const float lx = qb.x, ly = qb.y, okf = qb.z;
        float4 val;
        {
            float t, btm;
            t = v00.x + lx * (v01.x - v00.x); btm = v10.x + lx * (v11.x - v10.x);
            val.x = (t + ly * (btm - t)) * okf;
            t = v00.y + lx * (v01.y - v00.y); btm = v10.y + lx * (v11.y - v10.y);
            val.y = (t + ly * (btm - t)) * okf;
            t = v00.z + lx * (v01.z - v00.z); btm = v10.z + lx * (v11.z - v10.z);
            val.z = (t + ly * (btm - t)) * okf;
            t = v00.w + lx * (v01.w - v00.w); btm = v10.w + lx * (v11.w - v10.w);
            val.w = (t + ly * (btm - t)) * okf;
        }
        __stwt(out4 + (long)p * C4, val);     // streaming store, no L2 reuse

        p += 7;
        fp = nfp;
        qa = nqa; qb = nqb;
        v00 = n00; v01 = n01; v10 = n10; v11 = n11;
    }
}

extern "C" void kernel_launch(void* const* d_in, const int* in_sizes, int n_in,
                              void* d_out, int out_size)
{
    const float* boxes = (const float*)d_in[0];
    const float* f0    = (const float*)d_in[1];
    const float* f1    = (const float*)d_in[2];
    const float* f2    = (const float*)d_in[3];
    const float* f3    = (const float*)d_in[4];
    const float* f4    = (const float*)d_in[5];
    const int*   ishp  = (const int*)d_in[6];

    const int BN = in_sizes[0] / 4;                    // B*N boxes
    const int B  = in_sizes[1] / (256 * 256 * 256);    // feat0 = B*256*256*256
    const int N  = BN / B;

    // 2 blocks per SM (296 on a 148-SM GB300), each with <=7 contiguous boxes
    int grid = 296;
    if ((BN + 6) / 7 > grid) grid = (BN + 6) / 7;      // safety for larger BN
    const int chunk = BN / grid;
    const int rem   = BN % grid;

    roialign_kernel<<<grid, 448>>>(boxes, f0, f1, f2, f3, f4, ishp,
                                   (float*)d_out, N, BN, chunk, rem);
}

// round 8
// speedup vs baseline: 1.1110x; 1.1110x over previous
#include <cuda_runtime.h>

// RoiAlign FPN: B=2, N=1000, CROP=7x7, C=256, levels 256/128/64/32/16 (NHWC f32).
// One 256-thread block per box (high occupancy: target 6 CTAs/SM = 48 warps).
// Phase 1 (threads 0..48): per-pixel params into smem.
// Phase 2: 13 iters x 4 pixel-slots x 64 float4 channel groups; depth-1 load
// batches (4 LDG.128 in flight per thread), latency hidden by warp count.

#define C4 64  // 256 channels / 4

__global__ __launch_bounds__(256, 6) void roialign_kernel(
    const float* __restrict__ boxes,
    const float* __restrict__ f0, const float* __restrict__ f1,
    const float* __restrict__ f2, const float* __restrict__ f3,
    const float* __restrict__ f4,
    const int*   __restrict__ image_shape,
    float*       __restrict__ out,
    int N)
{
    __shared__ float4 s_a[49];                 // corner indices (int bitcast)
    __shared__ float4 s_b[49];                 // lx, ly, okf, 0
    __shared__ const float4* s_fp;             // selected level base pointer

    const int boxg = blockIdx.x;
    const int tid  = threadIdx.x;

    // ---------------- Phase 1: per-pixel params (threads 0..48) --------------
    if (tid < 49) {
        // NOTE: reference unpacks boxes[:,0] as "y1" though setup stacked
        // [x1,y1,x2,y2]; features are square so it's a consistent transpose.
        const float a0 = __ldg(boxes + (size_t)boxg * 4 + 0);
        const float a1 = __ldg(boxes + (size_t)boxg * 4 + 1);
        const float a2 = __ldg(boxes + (size_t)boxg * 4 + 2);
        const float a3 = __ldg(boxes + (size_t)boxg * 4 + 3);

        // lvl = clip(round(log2(sqrt(h*w) / (56/sqrt(area)))), 0, 4)
        const float h     = a3 - a1;
        const float w     = a2 - a0;
        const float area  = (float)(image_shape[0] * image_shape[1]);
        const float denom = 56.0f / sqrtf(area);
        int lvl = (int)rintf(log2f(sqrtf(h * w) / denom));  // round-half-even
        lvl = min(max(lvl, 0), 4);

        const int S = 256 >> lvl;
        const float* feat = (lvl == 0) ? f0 : (lvl == 1) ? f1
                          : (lvl == 2) ? f2 : (lvl == 3) ? f3 : f4;
        if (tid == 0) s_fp = (const float4*)feat;

        const float Hf = (float)(S - 1);
        const int gy = tid / 7;
        const int gx = tid % 7;

        // Exact reference op order: ys = y1*Hf + gy*((y2-y1)*Hf/6)
        const float ys = a0 * Hf + (float)gy * (((a2 - a0) * Hf) / 6.0f);
        const float xs = a1 * Hf + (float)gx * (((a3 - a1) * Hf) / 6.0f);

        const float y0f = floorf(ys);
        const float x0f = floorf(xs);
        const float ly  = ys - y0f;
        const float lx  = xs - x0f;

        const int y0 = (int)fminf(fmaxf(y0f,        0.0f), Hf);
        const int y1 = (int)fminf(fmaxf(y0f + 1.0f, 0.0f), Hf);
        const int x0 = (int)fminf(fmaxf(x0f,        0.0f), Hf);
        const int x1 = (int)fminf(fmaxf(x0f + 1.0f, 0.0f), Hf);

        const float okf = ((ys >= 0.0f) & (ys <= Hf) &
                           (xs >= 0.0f) & (xs <= Hf)) ? 1.0f : 0.0f;

        const int bS = (boxg / N) * S;
        const int r0 = (bS + y0) * S;
        const int r1 = (bS + y1) * S;
        // flat indices in float4 units (max ~8.4M, int32-safe)
        s_a[tid] = make_float4(__int_as_float((r0 + x0) * C4),
                               __int_as_float((r0 + x1) * C4),
                               __int_as_float((r1 + x0) * C4),
                               __int_as_float((r1 + x1) * C4));
        s_b[tid] = make_float4(lx, ly, okf, 0.0f);
    }
    __syncthreads();

    // ---------------- Phase 2: gather + lerp (register-lean) -----------------
    const float4* __restrict__ fp = s_fp;
    const int c    = tid & 63;        // float4 channel group 0..63
    const int psub = tid >> 6;        // pixel sub-slot 0..3
    float4* __restrict__ out4 = (float4*)out + (long)boxg * 49 * C4 + c;

    #pragma unroll
    for (int it = 0; it < 13; ++it) {
        const int p = it * 4 + psub;  // 0..51; last iter partially idle
        if (p < 49) {
            const float4 qa = s_a[p];
            const float4 qb = s_b[p];
            const float4 v00 = __ldg(fp + __float_as_int(qa.x) + c);
            const float4 v01 = __ldg(fp + __float_as_int(qa.y) + c);
            const float4 v10 = __ldg(fp + __float_as_int(qa.z) + c);
            const float4 v11 = __ldg(fp + __float_as_int(qa.w) + c);

            const float lx = qb.x, ly = qb.y, okf = qb.z;
            float4 val;
            {
                float t, btm;
                t = v00.x + lx * (v01.x - v00.x); btm = v10.x + lx * (v11.x - v10.x);
                val.x = (t + ly * (btm - t)) * okf;
                t = v00.y + lx * (v01.y - v00.y); btm = v10.y + lx * (v11.y - v10.y);
                val.y = (t + ly * (btm - t)) * okf;
                t = v00.z + lx * (v01.z - v00.z); btm = v10.z + lx * (v11.z - v10.z);
                val.z = (t + ly * (btm - t)) * okf;
                t = v00.w + lx * (v01.w - v00.w); btm = v10.w + lx * (v11.w - v10.w);
                val.w = (t + ly * (btm - t)) * okf;
            }
            out4[p * C4] = val;
        }
    }
}

extern "C" void kernel_launch(void* const* d_in, const int* in_sizes, int n_in,
                              void* d_out, int out_size)
{
    const float* boxes = (const float*)d_in[0];
    const float* f0    = (const float*)d_in[1];
    const float* f1    = (const float*)d_in[2];
    const float* f2    = (const float*)d_in[3];
    const float* f3    = (const float*)d_in[4];
    const float* f4    = (const float*)d_in[5];
    const int*   ishp  = (const int*)d_in[6];

    const int BN = in_sizes[0] / 4;                    // B*N boxes
    const int B  = in_sizes[1] / (256 * 256 * 256);    // feat0 = B*256*256*256
    const int N  = BN / B;

    roialign_kernel<<<BN, 256>>>(boxes, f0, f1, f2, f3, f4, ishp,
                                 (float*)d_out, N);
}

// round 9
// speedup vs baseline: 1.1304x; 1.0174x over previous
#include <cuda_runtime.h>

// RoiAlign FPN: B=2, N=1000, CROP=7x7, C=256, levels 256/128/64/32/16 (NHWC f32).
// 296 blocks x 448 threads; each block owns <=7 contiguous boxes.
// Phase 1: one thread per (box,pixel) computes all <=343 param sets into smem.
// Phase 2: outer box loop (unroll 1) x inner fully-unrolled 7 pixel-groups,
// depth-2 software pipeline carried ACROSS box boundaries (8 LDG.128 in
// flight/thread at all times; fp switch at compile-time j==6, no divisions).

#define C4 64  // 256 channels / 4

__global__ __launch_bounds__(448, 2) void roialign_kernel(
    const float* __restrict__ boxes,
    const float* __restrict__ f0, const float* __restrict__ f1,
    const float* __restrict__ f2, const float* __restrict__ f3,
    const float* __restrict__ f4,
    const int*   __restrict__ image_shape,
    float*       __restrict__ out,
    int N, int chunk, int rem)
{
    __shared__ float4 s_a[343];                // corner indices (int bitcast)
    __shared__ float4 s_b[343];                // lx, ly, okf, 0
    __shared__ const float4* s_fp[7];          // per-box level base pointer

    const int bid = blockIdx.x;
    const int tid = threadIdx.x;

    // contiguous box range: first `rem` blocks get chunk+1 boxes
    const int start = bid * chunk + min(bid, rem);
    const int nb    = chunk + (bid < rem ? 1 : 0);   // <= 7

    // ---------------- Phase 1: params for all nb*49 pixels -------------------
    if (tid < nb * 49) {
        const int bl   = tid / 49;             // box slot 0..nb-1
        const int pixl = tid % 49;
        const int boxg = start + bl;

        // NOTE: reference unpacks boxes[:,0] as "y1" though setup stacked
        // [x1,y1,x2,y2]; features are square so it's a consistent transpose.
        const float a0 = __ldg(boxes + (size_t)boxg * 4 + 0);
        const float a1 = __ldg(boxes + (size_t)boxg * 4 + 1);
        const float a2 = __ldg(boxes + (size_t)boxg * 4 + 2);
        const float a3 = __ldg(boxes + (size_t)boxg * 4 + 3);

        // lvl = clip(round(log2(sqrt(h*w) / (56/sqrt(area)))), 0, 4)
        const float h     = a3 - a1;
        const float w     = a2 - a0;
        const float area  = (float)(image_shape[0] * image_shape[1]);
        const float denom = 56.0f / sqrtf(area);
        int lvl = (int)rintf(log2f(sqrtf(h * w) / denom));  // round-half-even
        lvl = min(max(lvl, 0), 4);

        const int S = 256 >> lvl;
        const float* feat = (lvl == 0) ? f0 : (lvl == 1) ? f1
                          : (lvl == 2) ? f2 : (lvl == 3) ? f3 : f4;
        if (pixl == 0) s_fp[bl] = (const float4*)feat;

        const float Hf = (float)(S - 1);
        const int gy = pixl / 7;
        const int gx = pixl % 7;

        // Exact reference op order: ys = y1*Hf + gy*((y2-y1)*Hf/6)
        const float ys = a0 * Hf + (float)gy * (((a2 - a0) * Hf) / 6.0f);
        const float xs = a1 * Hf + (float)gx * (((a3 - a1) * Hf) / 6.0f);

        const float y0f = floorf(ys);
        const float x0f = floorf(xs);
        const float ly  = ys - y0f;
        const float lx  = xs - x0f;

        const int y0 = (int)fminf(fmaxf(y0f,        0.0f), Hf);
        const int y1 = (int)fminf(fmaxf(y0f + 1.0f, 0.0f), Hf);
        const int x0 = (int)fminf(fmaxf(x0f,        0.0f), Hf);
        const int x1 = (int)fminf(fmaxf(x0f + 1.0f, 0.0f), Hf);

        const float okf = ((ys >= 0.0f) & (ys <= Hf) &
                           (xs >= 0.0f) & (xs <= Hf)) ? 1.0f : 0.0f;

        const int bS = (boxg / N) * S;
        const int r0 = (bS + y0) * S;
        const int r1 = (bS + y1) * S;
        // flat indices in float4 units (max ~8.4M, int32-safe)
        s_a[tid] = make_float4(__int_as_float((r0 + x0) * C4),
                               __int_as_float((r0 + x1) * C4),
                               __int_as_float((r1 + x0) * C4),
                               __int_as_float((r1 + x1) * C4));
        s_b[tid] = make_float4(lx, ly, okf, 0.0f);
    }
    __syncthreads();

    // ---------------- Phase 2: pipelined gather + lerp -----------------------
    const int psub = tid >> 6;        // pixel sub-slot 0..6
    const int c    = tid & 63;        // float4 channel group 0..63
    const int last = nb * 49;         // one past last param index
    float4* __restrict__ out4 = (float4*)out + (long)start * 49 * C4 + c;

    // Prologue: pixel group 0 of box 0
    int p = psub;
    const float4* fp = s_fp[0];
    float4 qa = s_a[p];
    float4 qb = s_b[p];
    float4 v00 = __ldg(fp + __float_as_int(qa.x) + c);
    float4 v01 = __ldg(fp + __float_as_int(qa.y) + c);
    float4 v10 = __ldg(fp + __float_as_int(qa.z) + c);
    float4 v11 = __ldg(fp + __float_as_int(qa.w) + c);

    #pragma unroll 1
    for (int bl = 0; bl < nb; ++bl) {
        #pragma unroll
        for (int j = 0; j < 7; ++j) {
            // prefetch next pixel group (crosses box boundary at j==6)
            const float4* nfp;
            if (j < 6) {
                nfp = fp;
            } else {
                const int nbl = (bl + 1 < nb) ? bl + 1 : bl;
                nfp = s_fp[nbl];
            }
            const int np  = p + 7;
            const int npc = (np < last) ? np : p;   // clamped dummy at tail
            float4 nqa = s_a[npc];
            float4 nqb = s_b[npc];
            float4 n00 = __ldg(nfp + __float_as_int(nqa.x) + c);
            float4 n01 = __ldg(nfp + __float_as_int(nqa.y) + c);
            float4 n10 = __ldg(nfp + __float_as_int(nqa.z) + c);
            float4 n11 = __ldg(nfp + __float_as_int(nqa.w) + c);

            const float lx = qb.x, ly = qb.y, okf = qb.z;
            float4 val;
            {
                float t, btm;
                t = v00.x + lx * (v01.x - v00.x); btm = v10.x + lx * (v11.x - v10.x);
                val.x = (t + ly * (btm - t)) * okf;
                t = v00.y + lx * (v01.y - v00.y); btm = v10.y + lx * (v11.y - v10.y);
                val.y = (t + ly * (btm - t)) * okf;
                t = v00.z + lx * (v01.z - v00.z); btm = v10.z + lx * (v11.z - v10.z);
                val.z = (t + ly * (btm - t)) * okf;
                t = v00.w + lx * (v01.w - v00.w); btm = v10.w + lx * (v11.w - v10.w);
                val.w = (t + ly * (btm - t)) * okf;
            }
            out4[(long)p * C4] = val;

            p = np;
            fp = nfp;
            qa = nqa; qb = nqb;
            v00 = n00; v01 = n01; v10 = n10; v11 = n11;
        }
    }
}

extern "C" void kernel_launch(void* const* d_in, const int* in_sizes, int n_in,
                              void* d_out, int out_size)
{
    const float* boxes = (const float*)d_in[0];
    const float* f0    = (const float*)d_in[1];
    const float* f1    = (const float*)d_in[2];
    const float* f2    = (const float*)d_in[3];
    const float* f3    = (const float*)d_in[4];
    const float* f4    = (const float*)d_in[5];
    const int*   ishp  = (const int*)d_in[6];

    const int BN = in_sizes[0] / 4;                    // B*N boxes
    const int B  = in_sizes[1] / (256 * 256 * 256);    // feat0 = B*256*256*256
    const int N  = BN / B;

    // 2 blocks per SM (296 on 148-SM GB300), each with <=7 contiguous boxes
    int grid = 296;
    if ((BN + 6) / 7 > grid) grid = (BN + 6) / 7;      // safety for larger BN
    const int chunk = BN / grid;
    const int rem   = BN % grid;

    roialign_kernel<<<grid, 448>>>(boxes, f0, f1, f2, f3, f4, ishp,
                                   (float*)d_out, N, chunk, rem);
}